// round 5
// baseline (speedup 1.0000x reference)
#include <cuda_runtime.h>
#include <cuda_fp16.h>
#include <math.h>

#define N_USERS 100000
#define M_ITEMS 50000
#define N_ALL   150000
#define N_EDGES 4800000
#define DIM     64
#define NF2     (DIM / 2)           // 32 half2 / float2 per row
#define NF4     (DIM / 4)           // 16 float4 / uint2(=2xhalf2) per row
#define TOT_F2  (N_ALL * NF2)
#define TOT_F4  (N_ALL * NF4)

#define SCAN_BLK 1024
#define N_SCAN_BLOCKS ((N_ALL + SCAN_BLK - 1) / SCAN_BLK)   // 147

// ---- scratch (static device globals; no runtime allocation) ----
__device__ int    g_cnt[N_ALL];
__device__ int    g_off[N_ALL + 1];
__device__ int    g_cur[N_ALL];
__device__ int    g_bsums[256];
__device__ int2   g_edges[N_EDGES];       // packed (col, val-as-int)
__device__ float4 g_E0[TOT_F4];           // fp32 levels (exact recurrence)
__device__ float4 g_E1[TOT_F4];
__device__ float4 g_E2[TOT_F4];
__device__ uint2  g_H0[TOT_F4];           // fp16 shadows (gather sources), 8B = 4 dims
__device__ uint2  g_H1[TOT_F4];
__device__ uint2  g_H2[TOT_F4];

// ---------------------------------------------------------------------------
// E0 = concat(user_emb, item_emb) fp32 + fp16 shadow; zero degree counters
// ---------------------------------------------------------------------------
__global__ void concat_zero_kernel(const float4* __restrict__ u,
                                   const float4* __restrict__ it) {
    int i = blockIdx.x * blockDim.x + threadIdx.x;
    if (i < N_ALL) g_cnt[i] = 0;
    if (i >= TOT_F4) return;
    const int NU = N_USERS * NF4;
    float4 v = (i < NU) ? u[i] : it[i - NU];
    g_E0[i] = v;
    __half2 lo = __floats2half2_rn(v.x, v.y);
    __half2 hi = __floats2half2_rn(v.z, v.w);
    uint2 p;
    p.x = *(unsigned*)&lo;
    p.y = *(unsigned*)&hi;
    g_H0[i] = p;
}

// ---------------------------------------------------------------------------
// CSR build: histogram -> 2-level exclusive scan -> scatter
// ---------------------------------------------------------------------------
__global__ void hist_kernel(const int* __restrict__ rows) {
    int e = blockIdx.x * blockDim.x + threadIdx.x;
    if (e >= N_EDGES) return;
    atomicAdd(&g_cnt[rows[e]], 1);
}

__global__ void scan1_kernel() {
    __shared__ int sh[SCAN_BLK];
    int t = threadIdx.x;
    int g = blockIdx.x * SCAN_BLK + t;
    int v = (g < N_ALL) ? g_cnt[g] : 0;
    sh[t] = v;
    __syncthreads();
    #pragma unroll
    for (int d = 1; d < SCAN_BLK; d <<= 1) {
        int add = (t >= d) ? sh[t - d] : 0;
        __syncthreads();
        sh[t] += add;
        __syncthreads();
    }
    if (g < N_ALL) g_off[g] = sh[t] - v;
    if (t == SCAN_BLK - 1) g_bsums[blockIdx.x] = sh[t];
}

__global__ void scan2_kernel() {                    // 1 block, 256 threads
    __shared__ int sh[256];
    int t = threadIdx.x;
    int v = (t < N_SCAN_BLOCKS) ? g_bsums[t] : 0;
    sh[t] = v;
    __syncthreads();
    #pragma unroll
    for (int d = 1; d < 256; d <<= 1) {
        int add = (t >= d) ? sh[t - d] : 0;
        __syncthreads();
        sh[t] += add;
        __syncthreads();
    }
    g_bsums[t] = sh[t] - v;
}

__global__ void add_off_kernel() {
    int g = blockIdx.x * blockDim.x + threadIdx.x;
    if (g >= N_ALL) return;
    int o = g_off[g] + g_bsums[g / SCAN_BLK];
    g_off[g] = o;
    g_cur[g] = o;
    if (g == 0) g_off[N_ALL] = N_EDGES;
}

__global__ void scatter_kernel(const int*   __restrict__ rows,
                               const int*   __restrict__ cols,
                               const float* __restrict__ vals) {
    int e = blockIdx.x * blockDim.x + threadIdx.x;
    if (e >= N_EDGES) return;
    int p = atomicAdd(&g_cur[rows[e]], 1);
    g_edges[p] = make_int2(cols[e], __float_as_int(vals[e]));
}

// ---------------------------------------------------------------------------
// Warp-per-row CSR SpMM, 2 edges per warp instruction:
//   lanes 0-15 process even edges, lanes 16-31 odd edges; lane owns 4 dims (8B fp16).
//   Per 2 edges: 1 meta LDG.64 + 1 gather LDG.64. fp32 accumulation.
//   Final shfl_xor(16) merges the two half-warp edge streams.
// ---------------------------------------------------------------------------
__device__ __forceinline__ void facc(float4& a, uint2 raw, float v) {
    float2 lo = __half22float2(*(__half2*)&raw.x);
    float2 hi = __half22float2(*(__half2*)&raw.y);
    a.x += v * lo.x; a.y += v * lo.y;
    a.z += v * hi.x; a.w += v * hi.y;
}

__device__ __forceinline__ float4 spmm_row_acc(const uint2* __restrict__ src,
                                               int s, int e, int lane) {
    const int half = lane >> 4;      // 0: even edges, 1: odd edges
    const int sub  = lane & 15;      // 4-dim chunk within row
    float4 a0 = make_float4(0.f, 0.f, 0.f, 0.f);
    float4 a1 = make_float4(0.f, 0.f, 0.f, 0.f);
    float4 a2 = make_float4(0.f, 0.f, 0.f, 0.f);
    float4 a3 = make_float4(0.f, 0.f, 0.f, 0.f);
    int i = s;
    for (; i + 7 < e; i += 8) {
        int2 cv0 = __ldg(&g_edges[i     + half]);
        int2 cv1 = __ldg(&g_edges[i + 2 + half]);
        int2 cv2 = __ldg(&g_edges[i + 4 + half]);
        int2 cv3 = __ldg(&g_edges[i + 6 + half]);
        uint2 r0 = __ldg(src + (unsigned)cv0.x * NF4 + sub);
        uint2 r1 = __ldg(src + (unsigned)cv1.x * NF4 + sub);
        uint2 r2 = __ldg(src + (unsigned)cv2.x * NF4 + sub);
        uint2 r3 = __ldg(src + (unsigned)cv3.x * NF4 + sub);
        facc(a0, r0, __int_as_float(cv0.y));
        facc(a1, r1, __int_as_float(cv1.y));
        facc(a2, r2, __int_as_float(cv2.y));
        facc(a3, r3, __int_as_float(cv3.y));
    }
    for (; i < e; i += 2) {
        int myE = i + half;
        if (myE < e) {
            int2 cv = __ldg(&g_edges[myE]);
            uint2 r = __ldg(src + (unsigned)cv.x * NF4 + sub);
            facc(a0, r, __int_as_float(cv.y));
        }
    }
    float4 t;
    t.x = (a0.x + a1.x) + (a2.x + a3.x);
    t.y = (a0.y + a1.y) + (a2.y + a3.y);
    t.z = (a0.z + a1.z) + (a2.z + a3.z);
    t.w = (a0.w + a1.w) + (a2.w + a3.w);
    t.x += __shfl_xor_sync(0xffffffffu, t.x, 16);
    t.y += __shfl_xor_sync(0xffffffffu, t.y, 16);
    t.z += __shfl_xor_sync(0xffffffffu, t.z, 16);
    t.w += __shfl_xor_sync(0xffffffffu, t.w, 16);
    return t;
}

// dst = th1*spmm(srcH) - th3*prev  (fp32) + fp16 shadow of dst
__global__ __launch_bounds__(256)
void spmm_csr_kernel(const uint2*  __restrict__ srcH,
                     const float4* __restrict__ prev,
                     float4*       __restrict__ dst,
                     uint2*        __restrict__ dstH,
                     float th1, float th3) {
    int w    = (blockIdx.x * blockDim.x + threadIdx.x) >> 5;
    int lane = threadIdx.x & 31;
    if (w >= N_ALL) return;
    int s = __ldg(&g_off[w]);
    int e = __ldg(&g_off[w + 1]);
    float4 acc = spmm_row_acc(srcH, s, e, lane);
    int sub = lane & 15;
    float4 p = __ldg(prev + w * NF4 + sub);
    float4 r = make_float4(th1 * acc.x - th3 * p.x,
                           th1 * acc.y - th3 * p.y,
                           th1 * acc.z - th3 * p.z,
                           th1 * acc.w - th3 * p.w);
    if (lane < 16) {
        dst[w * NF4 + sub] = r;
    } else {
        __half2 lo = __floats2half2_rn(r.x, r.y);
        __half2 hi = __floats2half2_rn(r.z, r.w);
        uint2 ph;
        ph.x = *(unsigned*)&lo;
        ph.y = *(unsigned*)&hi;
        dstH[w * NF4 + sub] = ph;
    }
}

// Last pass: e3 on the fly, fused band_stop/band_pass epilogue.
// Lanes 0-15 write band_stop, lanes 16-31 write band_pass.
__global__ __launch_bounds__(256)
void spmm_final_kernel(float4* __restrict__ out, float th1, float th3) {
    int w    = (blockIdx.x * blockDim.x + threadIdx.x) >> 5;
    int lane = threadIdx.x & 31;
    if (w >= N_ALL) return;
    int s = __ldg(&g_off[w]);
    int e = __ldg(&g_off[w + 1]);
    float4 acc = spmm_row_acc(g_H2, s, e, lane);
    int sub = lane & 15;
    float4 e0 = __ldg(g_E0 + w * NF4 + sub);
    float4 e1 = __ldg(g_E1 + w * NF4 + sub);
    float4 e2 = __ldg(g_E2 + w * NF4 + sub);
    float4 e3 = make_float4(th1 * acc.x - th3 * e1.x,
                            th1 * acc.y - th3 * e1.y,
                            th1 * acc.z - th3 * e1.z,
                            th1 * acc.w - th3 * e1.w);
    float4 bs = make_float4(0.25f * (e0.x + e1.x + e2.x + e3.x),
                            0.25f * (e0.y + e1.y + e2.y + e3.y),
                            0.25f * (e0.z + e1.z + e2.z + e3.z),
                            0.25f * (e0.w + e1.w + e2.w + e3.w));
    // out row = 128 floats = 32 float4: [band_stop(16) | band_pass(16)]
    if (lane < 16) {
        out[w * 32 + sub] = bs;
    } else {
        float4 bp = make_float4(tanhf(0.1f * e0.x - bs.x),
                                tanhf(0.1f * e0.y - bs.y),
                                tanhf(0.1f * e0.z - bs.z),
                                tanhf(0.1f * e0.w - bs.w));
        out[w * 32 + 16 + sub] = bp;
    }
}

// ---------------------------------------------------------------------------
extern "C" void kernel_launch(void* const* d_in, const int* in_sizes, int n_in,
                              void* d_out, int out_size) {
    const float4* u    = (const float4*)d_in[0];
    const float4* it   = (const float4*)d_in[1];
    const int*    rows = (const int*)  d_in[2];
    const int*    cols = (const int*)  d_in[3];
    const float*  vals = (const float*)d_in[4];
    float4* out = (float4*)d_out;

    float4 *E0, *E1, *E2;
    uint2 *H0, *H1, *H2;
    cudaGetSymbolAddress((void**)&E0, g_E0);
    cudaGetSymbolAddress((void**)&E1, g_E1);
    cudaGetSymbolAddress((void**)&E2, g_E2);
    cudaGetSymbolAddress((void**)&H0, g_H0);
    cudaGetSymbolAddress((void**)&H1, g_H1);
    cudaGetSymbolAddress((void**)&H2, g_H2);

    const int TPB = 256;
    const int ELEM_BLKS = (TOT_F4 + TPB - 1) / TPB;
    const int EDGE_BLKS = (N_EDGES + TPB - 1) / TPB;
    const int NODE_BLKS = (N_ALL + TPB - 1) / TPB;
    const int SPMM_BLKS = (N_ALL * 32 + TPB - 1) / TPB;   // warp per row

    // Jacobi(1,1) coefficients
    const float TH1_2 = 1.875f;
    const float TH3_2 = 0.75f;
    const float TH1_3 = 56.0f / 30.0f;
    const float TH3_3 = 0.8f;

    concat_zero_kernel<<<ELEM_BLKS, TPB>>>(u, it);

    hist_kernel<<<EDGE_BLKS, TPB>>>(rows);
    scan1_kernel<<<N_SCAN_BLOCKS, SCAN_BLK>>>();
    scan2_kernel<<<1, 256>>>();
    add_off_kernel<<<NODE_BLKS, TPB>>>();
    scatter_kernel<<<EDGE_BLKS, TPB>>>(rows, cols, vals);

    spmm_csr_kernel<<<SPMM_BLKS, TPB>>>(H0, E0, E1, H1, 1.0f, 0.0f);
    spmm_csr_kernel<<<SPMM_BLKS, TPB>>>(H1, E0, E2, H2, TH1_2, TH3_2);
    spmm_final_kernel<<<SPMM_BLKS, TPB>>>(out, TH1_3, TH3_3);
}

// round 6
// speedup vs baseline: 1.3316x; 1.3316x over previous
#include <cuda_runtime.h>
#include <cuda_fp16.h>
#include <math.h>

#define N_USERS 100000
#define M_ITEMS 50000
#define N_ALL   150000
#define N_EDGES 4800000
#define DIM     64
#define NF2     (DIM / 2)           // 32 half2/float2 per row
#define NF4     (DIM / 4)
#define TOT_F2  (N_ALL * NF2)
#define TOT_F4  (N_ALL * NF4)

#define SCAN_BLK 1024
#define N_SCAN_BLOCKS ((N_ALL + SCAN_BLK - 1) / SCAN_BLK)   // 147

// ---- scratch (static device globals; no runtime allocation) ----
__device__ int     g_cnt[N_ALL];
__device__ int     g_off[N_ALL + 1];
__device__ int     g_cur[N_ALL];
__device__ int     g_bsums[256];
__device__ int2    g_edges[N_EDGES];       // packed (col, val-as-int)
__device__ float2  g_E0[TOT_F2];           // fp32 levels (exact recurrence)
__device__ float2  g_E1[TOT_F2];
__device__ float2  g_E2[TOT_F2];
__device__ __half2 g_H0[TOT_F2];           // fp16 shadows (gather sources)
__device__ __half2 g_H1[TOT_F2];
__device__ __half2 g_H2[TOT_F2];

// ---------------------------------------------------------------------------
// E0 = concat(user_emb, item_emb) fp32 + fp16 shadow; zero degree counters
// ---------------------------------------------------------------------------
__global__ void concat_zero_kernel(const float4* __restrict__ u,
                                   const float4* __restrict__ it) {
    int i = blockIdx.x * blockDim.x + threadIdx.x;
    if (i < N_ALL) g_cnt[i] = 0;
    if (i >= TOT_F4) return;
    const int NU = N_USERS * NF4;
    float4 v = (i < NU) ? u[i] : it[i - NU];
    ((float4*)g_E0)[i] = v;
    g_H0[2 * i]     = __floats2half2_rn(v.x, v.y);
    g_H0[2 * i + 1] = __floats2half2_rn(v.z, v.w);
}

// ---------------------------------------------------------------------------
// CSR build: histogram -> 2-level exclusive scan -> scatter
// ---------------------------------------------------------------------------
__global__ void hist_kernel(const int* __restrict__ rows) {
    int e = blockIdx.x * blockDim.x + threadIdx.x;
    if (e >= N_EDGES) return;
    atomicAdd(&g_cnt[rows[e]], 1);
}

__global__ void scan1_kernel() {
    __shared__ int sh[SCAN_BLK];
    int t = threadIdx.x;
    int g = blockIdx.x * SCAN_BLK + t;
    int v = (g < N_ALL) ? g_cnt[g] : 0;
    sh[t] = v;
    __syncthreads();
    #pragma unroll
    for (int d = 1; d < SCAN_BLK; d <<= 1) {
        int add = (t >= d) ? sh[t - d] : 0;
        __syncthreads();
        sh[t] += add;
        __syncthreads();
    }
    if (g < N_ALL) g_off[g] = sh[t] - v;
    if (t == SCAN_BLK - 1) g_bsums[blockIdx.x] = sh[t];
}

__global__ void scan2_kernel() {                    // 1 block, 256 threads
    __shared__ int sh[256];
    int t = threadIdx.x;
    int v = (t < N_SCAN_BLOCKS) ? g_bsums[t] : 0;
    sh[t] = v;
    __syncthreads();
    #pragma unroll
    for (int d = 1; d < 256; d <<= 1) {
        int add = (t >= d) ? sh[t - d] : 0;
        __syncthreads();
        sh[t] += add;
        __syncthreads();
    }
    g_bsums[t] = sh[t] - v;
}

__global__ void add_off_kernel() {
    int g = blockIdx.x * blockDim.x + threadIdx.x;
    if (g >= N_ALL) return;
    int o = g_off[g] + g_bsums[g / SCAN_BLK];
    g_off[g] = o;
    g_cur[g] = o;
    if (g == 0) g_off[N_ALL] = N_EDGES;
}

__global__ void scatter_kernel(const int*   __restrict__ rows,
                               const int*   __restrict__ cols,
                               const float* __restrict__ vals) {
    int e = blockIdx.x * blockDim.x + threadIdx.x;
    if (e >= N_EDGES) return;
    int p = atomicAdd(&g_cur[rows[e]], 1);
    g_edges[p] = make_int2(cols[e], __float_as_int(vals[e]));
}

// ---------------------------------------------------------------------------
// Warp-per-row CSR SpMM over the fp16 shadow, fp32 accumulation.
// lane handles 2 dims (half2 = 4B); per edge: 8B broadcast + 128B gather.
// 8-deep pipelining: 8 independent gathers in flight to cover L2 latency.
// ---------------------------------------------------------------------------
__device__ __forceinline__ void spmm_row_acc(const __half2* __restrict__ src,
                                             int s, int e, int lane,
                                             float2& acc) {
    float2 a0 = make_float2(0.f, 0.f);
    float2 a1 = make_float2(0.f, 0.f);
    float2 a2 = make_float2(0.f, 0.f);
    float2 a3 = make_float2(0.f, 0.f);
    int i = s;
    for (; i + 7 < e; i += 8) {
        int2 cv0 = __ldg(&g_edges[i]);
        int2 cv1 = __ldg(&g_edges[i + 1]);
        int2 cv2 = __ldg(&g_edges[i + 2]);
        int2 cv3 = __ldg(&g_edges[i + 3]);
        int2 cv4 = __ldg(&g_edges[i + 4]);
        int2 cv5 = __ldg(&g_edges[i + 5]);
        int2 cv6 = __ldg(&g_edges[i + 6]);
        int2 cv7 = __ldg(&g_edges[i + 7]);
        __half2 h0 = __ldg(src + (unsigned)cv0.x * NF2 + lane);
        __half2 h1 = __ldg(src + (unsigned)cv1.x * NF2 + lane);
        __half2 h2 = __ldg(src + (unsigned)cv2.x * NF2 + lane);
        __half2 h3 = __ldg(src + (unsigned)cv3.x * NF2 + lane);
        __half2 h4 = __ldg(src + (unsigned)cv4.x * NF2 + lane);
        __half2 h5 = __ldg(src + (unsigned)cv5.x * NF2 + lane);
        __half2 h6 = __ldg(src + (unsigned)cv6.x * NF2 + lane);
        __half2 h7 = __ldg(src + (unsigned)cv7.x * NF2 + lane);
        float2 x0 = __half22float2(h0);
        float2 x1 = __half22float2(h1);
        float2 x2 = __half22float2(h2);
        float2 x3 = __half22float2(h3);
        float v0 = __int_as_float(cv0.y);
        float v1 = __int_as_float(cv1.y);
        float v2 = __int_as_float(cv2.y);
        float v3 = __int_as_float(cv3.y);
        a0.x += v0 * x0.x; a0.y += v0 * x0.y;
        a1.x += v1 * x1.x; a1.y += v1 * x1.y;
        a2.x += v2 * x2.x; a2.y += v2 * x2.y;
        a3.x += v3 * x3.x; a3.y += v3 * x3.y;
        float2 x4 = __half22float2(h4);
        float2 x5 = __half22float2(h5);
        float2 x6 = __half22float2(h6);
        float2 x7 = __half22float2(h7);
        float v4 = __int_as_float(cv4.y);
        float v5 = __int_as_float(cv5.y);
        float v6 = __int_as_float(cv6.y);
        float v7 = __int_as_float(cv7.y);
        a0.x += v4 * x4.x; a0.y += v4 * x4.y;
        a1.x += v5 * x5.x; a1.y += v5 * x5.y;
        a2.x += v6 * x6.x; a2.y += v6 * x6.y;
        a3.x += v7 * x7.x; a3.y += v7 * x7.y;
    }
    for (; i < e; i++) {
        int2 cv = __ldg(&g_edges[i]);
        float2 x = __half22float2(__ldg(src + (unsigned)cv.x * NF2 + lane));
        float v = __int_as_float(cv.y);
        a0.x += v * x.x; a0.y += v * x.y;
    }
    acc.x = (a0.x + a1.x) + (a2.x + a3.x);
    acc.y = (a0.y + a1.y) + (a2.y + a3.y);
}

// dst = th1*spmm(srcH) - th3*prev  (fp32) + fp16 shadow of dst
__global__ __launch_bounds__(256)
void spmm_csr_kernel(const __half2* __restrict__ srcH,
                     const float2*  __restrict__ prev,
                     float2*        __restrict__ dst,
                     __half2*       __restrict__ dstH,
                     float th1, float th3) {
    int w    = (blockIdx.x * blockDim.x + threadIdx.x) >> 5;
    int lane = threadIdx.x & 31;
    if (w >= N_ALL) return;
    int s = __ldg(&g_off[w]);
    int e = __ldg(&g_off[w + 1]);
    float2 acc;
    spmm_row_acc(srcH, s, e, lane, acc);
    float2 p = __ldg(prev + w * NF2 + lane);
    float2 r = make_float2(th1 * acc.x - th3 * p.x,
                           th1 * acc.y - th3 * p.y);
    dst[w * NF2 + lane]  = r;
    dstH[w * NF2 + lane] = __floats2half2_rn(r.x, r.y);
}

// Last pass: e3 on the fly, fused band_stop/band_pass epilogue
__global__ __launch_bounds__(256)
void spmm_final_kernel(float2* __restrict__ out, float th1, float th3) {
    int w    = (blockIdx.x * blockDim.x + threadIdx.x) >> 5;
    int lane = threadIdx.x & 31;
    if (w >= N_ALL) return;
    int s = __ldg(&g_off[w]);
    int e = __ldg(&g_off[w + 1]);
    float2 acc;
    spmm_row_acc(g_H2, s, e, lane, acc);

    float2 e0 = __ldg(g_E0 + w * NF2 + lane);
    float2 e1 = __ldg(g_E1 + w * NF2 + lane);
    float2 e2 = __ldg(g_E2 + w * NF2 + lane);
    float2 e3 = make_float2(th1 * acc.x - th3 * e1.x,
                            th1 * acc.y - th3 * e1.y);
    float2 bs = make_float2(0.25f * (e0.x + e1.x + e2.x + e3.x),
                            0.25f * (e0.y + e1.y + e2.y + e3.y));
    float2 bp = make_float2(tanhf(0.1f * e0.x - bs.x),
                            tanhf(0.1f * e0.y - bs.y));
    out[w * 64 + lane]      = bs;
    out[w * 64 + 32 + lane] = bp;
}

// ---------------------------------------------------------------------------
extern "C" void kernel_launch(void* const* d_in, const int* in_sizes, int n_in,
                              void* d_out, int out_size) {
    const float4* u    = (const float4*)d_in[0];
    const float4* it   = (const float4*)d_in[1];
    const int*    rows = (const int*)  d_in[2];
    const int*    cols = (const int*)  d_in[3];
    const float*  vals = (const float*)d_in[4];
    float2* out = (float2*)d_out;

    float2 *E0, *E1, *E2;
    __half2 *H0, *H1, *H2;
    cudaGetSymbolAddress((void**)&E0, g_E0);
    cudaGetSymbolAddress((void**)&E1, g_E1);
    cudaGetSymbolAddress((void**)&E2, g_E2);
    cudaGetSymbolAddress((void**)&H0, g_H0);
    cudaGetSymbolAddress((void**)&H1, g_H1);
    cudaGetSymbolAddress((void**)&H2, g_H2);

    const int TPB = 256;
    const int ELEM_BLKS = (TOT_F4 + TPB - 1) / TPB;
    const int EDGE_BLKS = (N_EDGES + TPB - 1) / TPB;
    const int NODE_BLKS = (N_ALL + TPB - 1) / TPB;
    const int SPMM_BLKS = (N_ALL * 32 + TPB - 1) / TPB;   // warp per row

    // Jacobi(1,1) coefficients
    const float TH1_2 = 1.875f;
    const float TH3_2 = 0.75f;
    const float TH1_3 = 56.0f / 30.0f;
    const float TH3_3 = 0.8f;

    concat_zero_kernel<<<ELEM_BLKS, TPB>>>(u, it);

    hist_kernel<<<EDGE_BLKS, TPB>>>(rows);
    scan1_kernel<<<N_SCAN_BLOCKS, SCAN_BLK>>>();
    scan2_kernel<<<1, 256>>>();
    add_off_kernel<<<NODE_BLKS, TPB>>>();
    scatter_kernel<<<EDGE_BLKS, TPB>>>(rows, cols, vals);

    spmm_csr_kernel<<<SPMM_BLKS, TPB>>>(H0, E0, E1, H1, 1.0f, 0.0f);
    spmm_csr_kernel<<<SPMM_BLKS, TPB>>>(H1, E0, E2, H2, TH1_2, TH3_2);
    spmm_final_kernel<<<SPMM_BLKS, TPB>>>(out, TH1_3, TH3_3);
}